// round 6
// baseline (speedup 1.0000x reference)
#include <cuda_runtime.h>

#define BATCH 2048
#define IN_SZ 40960
#define HID 256
#define NF4 (BATCH * (IN_SZ / 4))
#define SCAN_CTAS 2048
#define SCAN_THREADS 256
#define SCAN_T (SCAN_CTAS * SCAN_THREADS)
#define SCAN_ITERS (NF4 / SCAN_T)

__device__ float g_ftw_t[(size_t)IN_SZ * HID];   // 41.9 MB transposed weights
__device__ int   g_cnt[2][BATCH];                // zero-init; self-cleaned by gather_mlp
__device__ int   g_idx[2][BATCH][32];

// ---------------------------------------------------------------------------
// Kernel 1: pure streaming scan of both one-hot arrays -> sparse index lists
// ---------------------------------------------------------------------------
__global__ __launch_bounds__(SCAN_THREADS) void scan(
    const float* __restrict__ white, const float* __restrict__ black)
{
    const int t = blockIdx.x * SCAN_THREADS + threadIdx.x;

#pragma unroll
    for (int p = 0; p < 2; ++p) {
        const uint4* src = reinterpret_cast<const uint4*>(p ? black : white);
        for (int it = 0; it < SCAN_ITERS; it += 8) {
            uint4 f[8];
#pragma unroll
            for (int u = 0; u < 8; ++u)
                f[u] = __ldcs(&src[t + (size_t)(it + u) * SCAN_T]);
#pragma unroll
            for (int u = 0; u < 8; ++u) {
                if (f[u].x | f[u].y | f[u].z | f[u].w) {
                    int v    = t + (it + u) * SCAN_T;
                    int row  = v / (IN_SZ / 4);
                    int base = (v - row * (IN_SZ / 4)) * 4;
                    if (f[u].x) { int s = atomicAdd(&g_cnt[p][row], 1); g_idx[p][row][s] = base + 0; }
                    if (f[u].y) { int s = atomicAdd(&g_cnt[p][row], 1); g_idx[p][row][s] = base + 1; }
                    if (f[u].z) { int s = atomicAdd(&g_cnt[p][row], 1); g_idx[p][row][s] = base + 2; }
                    if (f[u].w) { int s = atomicAdd(&g_cnt[p][row], 1); g_idx[p][row][s] = base + 3; }
                }
            }
        }
    }
}

// ---------------------------------------------------------------------------
// Kernel 2: transpose ft_w [256, 40960] -> g_ftw_t [40960, 256]
// MUST run strictly after scan: the 671 MB one-hot stream would otherwise
// evict g_ftw_t from L2 before the gather reads it (R5 regression).
// ---------------------------------------------------------------------------
__global__ __launch_bounds__(256) void transpose_ft(const float* __restrict__ ft_w) {
    __shared__ float tile[32][33];
    int x = blockIdx.x * 32 + threadIdx.x;
    int y = blockIdx.y * 32 + threadIdx.y;
#pragma unroll
    for (int k = 0; k < 32; k += 8)
        tile[threadIdx.y + k][threadIdx.x] = ft_w[(size_t)(y + k) * IN_SZ + x];
    __syncthreads();
    int ox = blockIdx.y * 32 + threadIdx.x;
    int oy = blockIdx.x * 32 + threadIdx.y;
#pragma unroll
    for (int k = 0; k < 32; k += 8)
        g_ftw_t[(size_t)(oy + k) * HID + ox] = tile[threadIdx.x][threadIdx.y + k];
}

// ---------------------------------------------------------------------------
// Kernel 3: float4 gather + fused MLP (float4 weight loads). One CTA per row.
// ---------------------------------------------------------------------------
__global__ __launch_bounds__(256) void gather_mlp(
    const float* __restrict__ stm,
    const float* __restrict__ ft_b,
    const float* __restrict__ l1w, const float* __restrict__ l1b,
    const float* __restrict__ l2w, const float* __restrict__ l2b,
    const float* __restrict__ l3w, const float* __restrict__ l3b,
    float* __restrict__ out)
{
    const int b   = blockIdx.x;
    const int tid = threadIdx.x;

    __shared__ int    widx[32], bidx[32];
    __shared__ int    cnts[2];
    __shared__ float4 red[2][4][64];
    __shared__ float  hid[2 * HID];
    __shared__ float  x1s[32];
    __shared__ float  x2s[32];

    if (tid < 32)      widx[tid]      = g_idx[0][b][tid];
    else if (tid < 64) bidx[tid - 32] = g_idx[1][b][tid - 32];
    // One thread per counter: read -> stash in shared -> zero (race-free self-clean).
    else if (tid == 64) { cnts[0] = g_cnt[0][b]; g_cnt[0][b] = 0; }
    else if (tid == 65) { cnts[1] = g_cnt[1][b]; g_cnt[1][b] = 0; }
    __syncthreads();

    const int wc = cnts[0];
    const int bc = cnts[1];

    const int c  = tid & 63;
    const int fg = tid >> 6;
    const float4* __restrict__ ftw4 = reinterpret_cast<const float4*>(g_ftw_t);

    float4 aw = make_float4(0.f, 0.f, 0.f, 0.f);
    float4 ab = make_float4(0.f, 0.f, 0.f, 0.f);
#pragma unroll 4
    for (int j = fg; j < wc; j += 4) {
        float4 v = ftw4[(size_t)widx[j] * 64 + c];
        aw.x += v.x; aw.y += v.y; aw.z += v.z; aw.w += v.w;
    }
#pragma unroll 4
    for (int j = fg; j < bc; j += 4) {
        float4 v = ftw4[(size_t)bidx[j] * 64 + c];
        ab.x += v.x; ab.y += v.y; ab.z += v.z; ab.w += v.w;
    }
    red[0][fg][c] = aw;
    red[1][fg][c] = ab;
    __syncthreads();

    const bool s = (stm[b] != 0.f);

    if (tid < 128) {
        int p  = tid >> 6;
        int cc = tid & 63;
        float4 v0 = red[p][0][cc], v1 = red[p][1][cc];
        float4 v2 = red[p][2][cc], v3 = red[p][3][cc];
        float4 bi = reinterpret_cast<const float4*>(ft_b)[cc];
        float4 r;
        r.x = fminf(fmaxf(v0.x + v1.x + v2.x + v3.x + bi.x, 0.f), 1.f);
        r.y = fminf(fmaxf(v0.y + v1.y + v2.y + v3.y + bi.y, 0.f), 1.f);
        r.z = fminf(fmaxf(v0.z + v1.z + v2.z + v3.z + bi.z, 0.f), 1.f);
        r.w = fminf(fmaxf(v0.w + v1.w + v2.w + v3.w + bi.w, 0.f), 1.f);
        int half = ((p == 0) == s) ? 0 : 1;
        reinterpret_cast<float4*>(hid)[half * 64 + cc] = r;
    }
    __syncthreads();

    // Layer 1: 512 -> 32, 8 threads per output, float4 loads
    {
        int k  = tid >> 3;
        int s8 = tid & 7;
        const float4* __restrict__ w4 = reinterpret_cast<const float4*>(l1w) + k * 128;
        const float4* h4 = reinterpret_cast<const float4*>(hid);
        float p = 0.f;
#pragma unroll
        for (int i = 0; i < 16; ++i) {
            float4 w = w4[s8 + 8 * i];
            float4 h = h4[s8 + 8 * i];
            p += w.x * h.x + w.y * h.y + w.z * h.z + w.w * h.w;
        }
        p += __shfl_down_sync(0xffffffffu, p, 4, 8);
        p += __shfl_down_sync(0xffffffffu, p, 2, 8);
        p += __shfl_down_sync(0xffffffffu, p, 1, 8);
        if (s8 == 0) x1s[k] = fminf(fmaxf(p + l1b[k], 0.f), 1.f);
    }
    __syncthreads();

    // Layer 2: 32 -> 32 (float4 loads)
    if (tid < 32) {
        const float4* w4 = reinterpret_cast<const float4*>(l2w) + tid * 8;
        const float4* x4 = reinterpret_cast<const float4*>(x1s);
        float p = l2b[tid];
#pragma unroll
        for (int i = 0; i < 8; ++i) {
            float4 w = w4[i];
            float4 x = x4[i];
            p += w.x * x.x + w.y * x.y + w.z * x.z + w.w * x.w;
        }
        x2s[tid] = fminf(fmaxf(p, 0.f), 1.f);
    }
    __syncwarp(0xffffffffu);

    // Layer 3: 32 -> 1
    if (tid < 32) {
        float p = x2s[tid] * l3w[tid];
        p += __shfl_down_sync(0xffffffffu, p, 16);
        p += __shfl_down_sync(0xffffffffu, p, 8);
        p += __shfl_down_sync(0xffffffffu, p, 4);
        p += __shfl_down_sync(0xffffffffu, p, 2);
        p += __shfl_down_sync(0xffffffffu, p, 1);
        if (tid == 0) out[b] = p + l3b[0];
    }
}

// ---------------------------------------------------------------------------
// Launch
// ---------------------------------------------------------------------------
extern "C" void kernel_launch(void* const* d_in, const int* in_sizes, int n_in,
                              void* d_out, int out_size) {
    const float* white = (const float*)d_in[0];
    const float* black = (const float*)d_in[1];
    const float* stm   = (const float*)d_in[2];
    const float* ft_w  = (const float*)d_in[3];
    const float* ft_b  = (const float*)d_in[4];
    const float* l1w   = (const float*)d_in[5];
    const float* l1b   = (const float*)d_in[6];
    const float* l2w   = (const float*)d_in[7];
    const float* l2b   = (const float*)d_in[8];
    const float* l3w   = (const float*)d_in[9];
    const float* l3b   = (const float*)d_in[10];
    float* out = (float*)d_out;

    scan<<<SCAN_CTAS, SCAN_THREADS>>>(white, black);

    dim3 tb(32, 8);
    dim3 tg(IN_SZ / 32, HID / 32);
    transpose_ft<<<tg, tb>>>(ft_w);

    gather_mlp<<<BATCH, 256>>>(stm, ft_b, l1w, l1b, l2w, l2b, l3w, l3b, out);
}

// round 7
// speedup vs baseline: 1.0561x; 1.0561x over previous
#include <cuda_runtime.h>

#define BATCH 2048
#define IN_SZ 40960
#define HID 256
#define NF4 (BATCH * (IN_SZ / 4))
#define SCAN_CTAS 2048
#define SCAN_THREADS 256
#define SCAN_T (SCAN_CTAS * SCAN_THREADS)
#define SCAN_ITERS (NF4 / SCAN_T)
#define ROWS 16                       // rows per MLP CTA
#define MLP_CTAS (BATCH / ROWS)       // 128

__device__ float g_ftw_t[(size_t)IN_SZ * HID];   // 41.9 MB transposed weights
__device__ int   g_cnt[2][BATCH];                // zero-init; self-cleaned by gather_ft
__device__ int   g_idx[2][BATCH][32];
__device__ float g_hid[(size_t)BATCH * 2 * HID]; // 4 MB hidden activations

// ---------------------------------------------------------------------------
// Kernel 1: streaming scan of both one-hot arrays -> sparse index lists
// ---------------------------------------------------------------------------
__global__ __launch_bounds__(SCAN_THREADS) void scan(
    const float* __restrict__ white, const float* __restrict__ black)
{
    const int t = blockIdx.x * SCAN_THREADS + threadIdx.x;

#pragma unroll
    for (int p = 0; p < 2; ++p) {
        const uint4* src = reinterpret_cast<const uint4*>(p ? black : white);
        for (int it = 0; it < SCAN_ITERS; it += 8) {
            uint4 f[8];
#pragma unroll
            for (int u = 0; u < 8; ++u)
                f[u] = __ldcs(&src[t + (size_t)(it + u) * SCAN_T]);
#pragma unroll
            for (int u = 0; u < 8; ++u) {
                if (f[u].x | f[u].y | f[u].z | f[u].w) {
                    int v    = t + (it + u) * SCAN_T;
                    int row  = v / (IN_SZ / 4);
                    int base = (v - row * (IN_SZ / 4)) * 4;
                    if (f[u].x) { int s = atomicAdd(&g_cnt[p][row], 1); g_idx[p][row][s] = base + 0; }
                    if (f[u].y) { int s = atomicAdd(&g_cnt[p][row], 1); g_idx[p][row][s] = base + 1; }
                    if (f[u].z) { int s = atomicAdd(&g_cnt[p][row], 1); g_idx[p][row][s] = base + 2; }
                    if (f[u].w) { int s = atomicAdd(&g_cnt[p][row], 1); g_idx[p][row][s] = base + 3; }
                }
            }
        }
    }
}

// ---------------------------------------------------------------------------
// Kernel 2: transpose ft_w [256, 40960] -> g_ftw_t [40960, 256]
// Runs strictly after scan so g_ftw_t stays L2-resident for the gather.
// ---------------------------------------------------------------------------
__global__ __launch_bounds__(256) void transpose_ft(const float* __restrict__ ft_w) {
    __shared__ float tile[32][33];
    int x = blockIdx.x * 32 + threadIdx.x;
    int y = blockIdx.y * 32 + threadIdx.y;
#pragma unroll
    for (int k = 0; k < 32; k += 8)
        tile[threadIdx.y + k][threadIdx.x] = ft_w[(size_t)(y + k) * IN_SZ + x];
    __syncthreads();
    int ox = blockIdx.y * 32 + threadIdx.x;
    int oy = blockIdx.x * 32 + threadIdx.y;
#pragma unroll
    for (int k = 0; k < 32; k += 8)
        g_ftw_t[(size_t)(oy + k) * HID + ox] = tile[threadIdx.x][threadIdx.y + k];
}

// ---------------------------------------------------------------------------
// Kernel 3: gather only (R3's proven loop). Writes clipped, stm-ordered
// hidden row to g_hid. No l1w traffic here.
// ---------------------------------------------------------------------------
__global__ __launch_bounds__(256) void gather_ft(
    const float* __restrict__ stm, const float* __restrict__ ft_b)
{
    const int b   = blockIdx.x;
    const int tid = threadIdx.x;

    __shared__ int    widx[32], bidx[32];
    __shared__ int    cnts[2];
    __shared__ float4 red[2][4][64];

    if (tid < 32)      widx[tid]      = g_idx[0][b][tid];
    else if (tid < 64) bidx[tid - 32] = g_idx[1][b][tid - 32];
    else if (tid == 64) { cnts[0] = g_cnt[0][b]; g_cnt[0][b] = 0; }
    else if (tid == 65) { cnts[1] = g_cnt[1][b]; g_cnt[1][b] = 0; }
    __syncthreads();

    const int wc = cnts[0];
    const int bc = cnts[1];

    const int c  = tid & 63;
    const int fg = tid >> 6;
    const float4* __restrict__ ftw4 = reinterpret_cast<const float4*>(g_ftw_t);

    float4 aw = make_float4(0.f, 0.f, 0.f, 0.f);
    float4 ab = make_float4(0.f, 0.f, 0.f, 0.f);
#pragma unroll 4
    for (int j = fg; j < wc; j += 4) {
        float4 v = ftw4[(size_t)widx[j] * 64 + c];
        aw.x += v.x; aw.y += v.y; aw.z += v.z; aw.w += v.w;
    }
#pragma unroll 4
    for (int j = fg; j < bc; j += 4) {
        float4 v = ftw4[(size_t)bidx[j] * 64 + c];
        ab.x += v.x; ab.y += v.y; ab.z += v.z; ab.w += v.w;
    }
    red[0][fg][c] = aw;
    red[1][fg][c] = ab;
    __syncthreads();

    const bool s = (stm[b] != 0.f);

    if (tid < 128) {
        int p  = tid >> 6;
        int cc = tid & 63;
        float4 v0 = red[p][0][cc], v1 = red[p][1][cc];
        float4 v2 = red[p][2][cc], v3 = red[p][3][cc];
        float4 bi = reinterpret_cast<const float4*>(ft_b)[cc];
        float4 r;
        r.x = fminf(fmaxf(v0.x + v1.x + v2.x + v3.x + bi.x, 0.f), 1.f);
        r.y = fminf(fmaxf(v0.y + v1.y + v2.y + v3.y + bi.y, 0.f), 1.f);
        r.z = fminf(fmaxf(v0.z + v1.z + v2.z + v3.z + bi.z, 0.f), 1.f);
        r.w = fminf(fmaxf(v0.w + v1.w + v2.w + v3.w + bi.w, 0.f), 1.f);
        int half = ((p == 0) == s) ? 0 : 1;
        reinterpret_cast<float4*>(g_hid)[(size_t)b * 128 + half * 64 + cc] = r;
    }
}

// ---------------------------------------------------------------------------
// Kernel 4: batched MLP, 16 rows per CTA, l1w staged once into shared
// (transposed, padded stride 33 -> conflict-free lane reads).
// Dynamic smem: wt 512*33 + hs 16*516 + part 8*16*32 floats = 116,992 B.
// ---------------------------------------------------------------------------
#define WT_STRIDE 33
#define HS_STRIDE 516
#define MLP_SMEM ((512 * WT_STRIDE + ROWS * HS_STRIDE + 8 * ROWS * 32) * 4)

__global__ __launch_bounds__(256) void mlp(
    const float* __restrict__ l1w, const float* __restrict__ l1b,
    const float* __restrict__ l2w, const float* __restrict__ l2b,
    const float* __restrict__ l3w, const float* __restrict__ l3b,
    float* __restrict__ out)
{
    extern __shared__ float sm[];
    float* wt   = sm;                          // [512][33]: wt[j*33+k] = l1w[k][j]
    float* hs   = sm + 512 * WT_STRIDE;        // [16][516]
    float* part = hs + ROWS * HS_STRIDE;       // [8][16][32]
    __shared__ float x1[ROWS][32];
    __shared__ float x2[ROWS][32];

    const int tid  = threadIdx.x;
    const int row0 = blockIdx.x * ROWS;

    // Stage l1w [32][512] transposed into shared.
    const float4* l1w4 = reinterpret_cast<const float4*>(l1w);
    for (int idx = tid; idx < 32 * 128; idx += 256) {
        int k = idx >> 7, j4 = idx & 127;
        float4 w = l1w4[idx];
        int j = 4 * j4;
        wt[(j + 0) * WT_STRIDE + k] = w.x;
        wt[(j + 1) * WT_STRIDE + k] = w.y;
        wt[(j + 2) * WT_STRIDE + k] = w.z;
        wt[(j + 3) * WT_STRIDE + k] = w.w;
    }
    // Stage this CTA's 16 hidden rows.
    const float4* hid4 = reinterpret_cast<const float4*>(g_hid + (size_t)row0 * 512);
    for (int idx = tid; idx < ROWS * 128; idx += 256) {
        int r = idx >> 7, j4 = idx & 127;
        float4 h = hid4[idx];
        int j = 4 * j4;
        hs[r * HS_STRIDE + j + 0] = h.x;
        hs[r * HS_STRIDE + j + 1] = h.y;
        hs[r * HS_STRIDE + j + 2] = h.z;
        hs[r * HS_STRIDE + j + 3] = h.w;
    }
    __syncthreads();

    // Layer 1 partials: warp w owns j in [64w, 64w+64); lane = output k;
    // 16 row-accumulators in registers.
    {
        int w = tid >> 5, lane = tid & 31;
        float acc[ROWS];
#pragma unroll
        for (int r = 0; r < ROWS; ++r) acc[r] = 0.f;
        int j0 = w * 64;
        for (int j = j0; j < j0 + 64; ++j) {
            float wv = wt[j * WT_STRIDE + lane];
#pragma unroll
            for (int r = 0; r < ROWS; ++r)
                acc[r] += hs[r * HS_STRIDE + j] * wv;
        }
#pragma unroll
        for (int r = 0; r < ROWS; ++r)
            part[(w * ROWS + r) * 32 + lane] = acc[r];
    }
    __syncthreads();

    // Reduce across 8 warps + bias + clip -> x1
    for (int idx = tid; idx < ROWS * 32; idx += 256) {
        int r = idx >> 5, k = idx & 31;
        float p = l1b[k];
#pragma unroll
        for (int w = 0; w < 8; ++w) p += part[(w * ROWS + r) * 32 + k];
        x1[r][k] = fminf(fmaxf(p, 0.f), 1.f);
    }
    __syncthreads();

    // Layer 2: 32 -> 32 for all rows
    for (int idx = tid; idx < ROWS * 32; idx += 256) {
        int r = idx >> 5, k = idx & 31;
        float p = l2b[k];
        const float* w = l2w + k * 32;
#pragma unroll
        for (int j = 0; j < 32; ++j) p += x1[r][j] * w[j];
        x2[r][k] = fminf(fmaxf(p, 0.f), 1.f);
    }
    __syncthreads();

    // Layer 3: 32 -> 1 per row
    if (tid < ROWS) {
        float p = l3b[0];
#pragma unroll
        for (int j = 0; j < 32; ++j) p += x2[tid][j] * l3w[j];
        out[row0 + tid] = p;
    }
}

// ---------------------------------------------------------------------------
// Launch
// ---------------------------------------------------------------------------
extern "C" void kernel_launch(void* const* d_in, const int* in_sizes, int n_in,
                              void* d_out, int out_size) {
    const float* white = (const float*)d_in[0];
    const float* black = (const float*)d_in[1];
    const float* stm   = (const float*)d_in[2];
    const float* ft_w  = (const float*)d_in[3];
    const float* ft_b  = (const float*)d_in[4];
    const float* l1w   = (const float*)d_in[5];
    const float* l1b   = (const float*)d_in[6];
    const float* l2w   = (const float*)d_in[7];
    const float* l2b   = (const float*)d_in[8];
    const float* l3w   = (const float*)d_in[9];
    const float* l3b   = (const float*)d_in[10];
    float* out = (float*)d_out;

    static bool smem_set = false;
    if (!smem_set) {
        cudaFuncSetAttribute(mlp, cudaFuncAttributeMaxDynamicSharedMemorySize, MLP_SMEM);
        smem_set = true;
    }

    scan<<<SCAN_CTAS, SCAN_THREADS>>>(white, black);

    dim3 tb(32, 8);
    dim3 tg(IN_SZ / 32, HID / 32);
    transpose_ft<<<tg, tb>>>(ft_w);

    gather_ft<<<BATCH, 256>>>(stm, ft_b);

    mlp<<<MLP_CTAS, 256, MLP_SMEM>>>(l1w, l1b, l2w, l2b, l3w, l3b, out);
}

// round 8
// speedup vs baseline: 1.3019x; 1.2328x over previous
#include <cuda_runtime.h>

#define BATCH 2048
#define IN_SZ 40960
#define HID 256
#define ROW_F4 (IN_SZ / 4)          // 10240 uint4 per one-hot row
#define ROW_ITERS (ROW_F4 / 256)    // 40 iterations per perspective

__device__ float g_ftw_t[(size_t)IN_SZ * HID];   // 41.9 MB transposed weights

// ---------------------------------------------------------------------------
// Kernel 1: transpose ft_w [256, 40960] -> g_ftw_t [40960, 256]
// ---------------------------------------------------------------------------
__global__ __launch_bounds__(256) void transpose_ft(const float* __restrict__ ft_w) {
    __shared__ float tile[32][33];
    int x = blockIdx.x * 32 + threadIdx.x;
    int y = blockIdx.y * 32 + threadIdx.y;
#pragma unroll
    for (int k = 0; k < 32; k += 8)
        tile[threadIdx.y + k][threadIdx.x] = ft_w[(size_t)(y + k) * IN_SZ + x];
    __syncthreads();
    int ox = blockIdx.y * 32 + threadIdx.x;
    int oy = blockIdx.x * 32 + threadIdx.y;
#pragma unroll
    for (int k = 0; k < 32; k += 8)
        g_ftw_t[(size_t)(oy + k) * HID + ox] = tile[threadIdx.x][threadIdx.y + k];
}

// ---------------------------------------------------------------------------
// Kernel 2 (fused): one CTA per batch row.
//   Phase A: batch-8 streaming scan of this row's white/black one-hots,
//            nonzero indices pushed to shared (smem atomics).
//   Phase B: float4 gather from L2-hot g_ftw_t, bias+clip, stm-ordered hid.
//   Phase C: scalar MLP (R3's proven shape — overlaps other CTAs' streams).
// ---------------------------------------------------------------------------
__global__ __launch_bounds__(256) void nnue_fused(
    const float* __restrict__ white, const float* __restrict__ black,
    const float* __restrict__ stm,
    const float* __restrict__ ft_b,
    const float* __restrict__ l1w, const float* __restrict__ l1b,
    const float* __restrict__ l2w, const float* __restrict__ l2b,
    const float* __restrict__ l3w, const float* __restrict__ l3b,
    float* __restrict__ out)
{
    const int b   = blockIdx.x;
    const int tid = threadIdx.x;

    __shared__ int    cnt[2];
    __shared__ int    idx[2][32];
    __shared__ float4 red[2][4][64];
    __shared__ float  hid[2 * HID];
    __shared__ float  x1s[32];
    __shared__ float  x2s[32];

    if (tid < 2) cnt[tid] = 0;
    __syncthreads();

    // ---- Phase A: scan both perspectives, batch-8 streaming loads ----
#pragma unroll
    for (int p = 0; p < 2; ++p) {
        const uint4* src = reinterpret_cast<const uint4*>(p ? black : white)
                         + (size_t)b * ROW_F4;
#pragma unroll
        for (int it = 0; it < ROW_ITERS; it += 8) {
            uint4 f[8];
#pragma unroll
            for (int u = 0; u < 8; ++u)
                f[u] = __ldcs(&src[(it + u) * 256 + tid]);
#pragma unroll
            for (int u = 0; u < 8; ++u) {
                if (f[u].x | f[u].y | f[u].z | f[u].w) {
                    int base = ((it + u) * 256 + tid) * 4;
                    if (f[u].x) { int s = atomicAdd(&cnt[p], 1); idx[p][s] = base + 0; }
                    if (f[u].y) { int s = atomicAdd(&cnt[p], 1); idx[p][s] = base + 1; }
                    if (f[u].z) { int s = atomicAdd(&cnt[p], 1); idx[p][s] = base + 2; }
                    if (f[u].w) { int s = atomicAdd(&cnt[p], 1); idx[p][s] = base + 3; }
                }
            }
        }
    }
    __syncthreads();

    const int wc = cnt[0];
    const int bc = cnt[1];

    // ---- Phase B: float4 gather ----
    const int c  = tid & 63;
    const int fg = tid >> 6;
    const float4* __restrict__ ftw4 = reinterpret_cast<const float4*>(g_ftw_t);

    float4 aw = make_float4(0.f, 0.f, 0.f, 0.f);
    float4 ab = make_float4(0.f, 0.f, 0.f, 0.f);
#pragma unroll 4
    for (int j = fg; j < wc; j += 4) {
        float4 v = ftw4[(size_t)idx[0][j] * 64 + c];
        aw.x += v.x; aw.y += v.y; aw.z += v.z; aw.w += v.w;
    }
#pragma unroll 4
    for (int j = fg; j < bc; j += 4) {
        float4 v = ftw4[(size_t)idx[1][j] * 64 + c];
        ab.x += v.x; ab.y += v.y; ab.z += v.z; ab.w += v.w;
    }
    red[0][fg][c] = aw;
    red[1][fg][c] = ab;
    __syncthreads();

    const bool s = (stm[b] != 0.f);

    if (tid < 128) {
        int p  = tid >> 6;
        int cc = tid & 63;
        float4 v0 = red[p][0][cc], v1 = red[p][1][cc];
        float4 v2 = red[p][2][cc], v3 = red[p][3][cc];
        float4 bi = reinterpret_cast<const float4*>(ft_b)[cc];
        float4 r;
        r.x = fminf(fmaxf(v0.x + v1.x + v2.x + v3.x + bi.x, 0.f), 1.f);
        r.y = fminf(fmaxf(v0.y + v1.y + v2.y + v3.y + bi.y, 0.f), 1.f);
        r.z = fminf(fmaxf(v0.z + v1.z + v2.z + v3.z + bi.z, 0.f), 1.f);
        r.w = fminf(fmaxf(v0.w + v1.w + v2.w + v3.w + bi.w, 0.f), 1.f);
        int half = ((p == 0) == s) ? 0 : 1;
        reinterpret_cast<float4*>(hid)[half * 64 + cc] = r;
    }
    __syncthreads();

    // ---- Phase C: MLP (R3's proven scalar shape) ----
    // Layer 1: 512 -> 32, 8 threads per output
    {
        int k  = tid >> 3;
        int s8 = tid & 7;
        const float* w = l1w + k * 512;
        float p = 0.f;
#pragma unroll
        for (int j = s8; j < 512; j += 8) p += hid[j] * w[j];
        p += __shfl_down_sync(0xffffffffu, p, 4, 8);
        p += __shfl_down_sync(0xffffffffu, p, 2, 8);
        p += __shfl_down_sync(0xffffffffu, p, 1, 8);
        if (s8 == 0) x1s[k] = fminf(fmaxf(p + l1b[k], 0.f), 1.f);
    }
    __syncthreads();

    // Layer 2: 32 -> 32
    if (tid < 32) {
        float p = l2b[tid];
        const float* w = l2w + tid * 32;
#pragma unroll
        for (int j = 0; j < 32; ++j) p += x1s[j] * w[j];
        x2s[tid] = fminf(fmaxf(p, 0.f), 1.f);
    }
    __syncwarp(0xffffffffu);

    // Layer 3: 32 -> 1
    if (tid < 32) {
        float p = x2s[tid] * l3w[tid];
        p += __shfl_down_sync(0xffffffffu, p, 16);
        p += __shfl_down_sync(0xffffffffu, p, 8);
        p += __shfl_down_sync(0xffffffffu, p, 4);
        p += __shfl_down_sync(0xffffffffu, p, 2);
        p += __shfl_down_sync(0xffffffffu, p, 1);
        if (tid == 0) out[b] = p + l3b[0];
    }
}

// ---------------------------------------------------------------------------
// Launch
// ---------------------------------------------------------------------------
extern "C" void kernel_launch(void* const* d_in, const int* in_sizes, int n_in,
                              void* d_out, int out_size) {
    const float* white = (const float*)d_in[0];
    const float* black = (const float*)d_in[1];
    const float* stm   = (const float*)d_in[2];
    const float* ft_w  = (const float*)d_in[3];
    const float* ft_b  = (const float*)d_in[4];
    const float* l1w   = (const float*)d_in[5];
    const float* l1b   = (const float*)d_in[6];
    const float* l2w   = (const float*)d_in[7];
    const float* l2b   = (const float*)d_in[8];
    const float* l3w   = (const float*)d_in[9];
    const float* l3b   = (const float*)d_in[10];
    float* out = (float*)d_out;

    dim3 tb(32, 8);
    dim3 tg(IN_SZ / 32, HID / 32);
    transpose_ft<<<tg, tb>>>(ft_w);

    nnue_fused<<<BATCH, 256>>>(white, black, stm, ft_b,
                               l1w, l1b, l2w, l2b, l3w, l3b, out);
}

// round 9
// speedup vs baseline: 1.3030x; 1.0009x over previous
#include <cuda_runtime.h>

#define BATCH 2048
#define IN_SZ 40960
#define HID 256
#define ROW_F4 (IN_SZ / 4)          // 10240 uint4 per one-hot row
#define ROW_ITERS (ROW_F4 / 256)    // 40 iterations per perspective

__device__ float g_ftw_t[(size_t)IN_SZ * HID];   // 41.9 MB transposed weights

// ---------------------------------------------------------------------------
// Kernel 1: transpose ft_w [256, 40960] -> g_ftw_t [40960, 256]
// ---------------------------------------------------------------------------
__global__ __launch_bounds__(256) void transpose_ft(const float* __restrict__ ft_w) {
    __shared__ float tile[32][33];
    int x = blockIdx.x * 32 + threadIdx.x;
    int y = blockIdx.y * 32 + threadIdx.y;
#pragma unroll
    for (int k = 0; k < 32; k += 8)
        tile[threadIdx.y + k][threadIdx.x] = ft_w[(size_t)(y + k) * IN_SZ + x];
    __syncthreads();
    int ox = blockIdx.y * 32 + threadIdx.x;
    int oy = blockIdx.x * 32 + threadIdx.y;
#pragma unroll
    for (int k = 0; k < 32; k += 8)
        g_ftw_t[(size_t)(oy + k) * HID + ox] = tile[threadIdx.x][threadIdx.y + k];
}

// ---------------------------------------------------------------------------
// Kernel 2 (fused): one CTA per batch row; batch-4 scan to fit 32 regs
// so 8 CTAs are resident per SM (tail hiding under other CTAs' streams).
// ---------------------------------------------------------------------------
__global__ __launch_bounds__(256, 8) void nnue_fused(
    const float* __restrict__ white, const float* __restrict__ black,
    const float* __restrict__ stm,
    const float* __restrict__ ft_b,
    const float* __restrict__ l1w, const float* __restrict__ l1b,
    const float* __restrict__ l2w, const float* __restrict__ l2b,
    const float* __restrict__ l3w, const float* __restrict__ l3b,
    float* __restrict__ out)
{
    const int b   = blockIdx.x;
    const int tid = threadIdx.x;

    __shared__ int    cnt[2];
    __shared__ int    idx[2][32];
    __shared__ float4 red[2][4][64];
    __shared__ float  hid[2 * HID];
    __shared__ float  x1s[32];
    __shared__ float  x2s[32];

    if (tid < 2) cnt[tid] = 0;
    __syncthreads();

    // ---- Phase A: scan both perspectives, batch-4 streaming loads ----
#pragma unroll
    for (int p = 0; p < 2; ++p) {
        const uint4* src = reinterpret_cast<const uint4*>(p ? black : white)
                         + (size_t)b * ROW_F4;
#pragma unroll 2
        for (int it = 0; it < ROW_ITERS; it += 4) {
            uint4 f[4];
#pragma unroll
            for (int u = 0; u < 4; ++u)
                f[u] = __ldcs(&src[(it + u) * 256 + tid]);
#pragma unroll
            for (int u = 0; u < 4; ++u) {
                if (f[u].x | f[u].y | f[u].z | f[u].w) {
                    int base = ((it + u) * 256 + tid) * 4;
                    if (f[u].x) { int s = atomicAdd(&cnt[p], 1); idx[p][s] = base + 0; }
                    if (f[u].y) { int s = atomicAdd(&cnt[p], 1); idx[p][s] = base + 1; }
                    if (f[u].z) { int s = atomicAdd(&cnt[p], 1); idx[p][s] = base + 2; }
                    if (f[u].w) { int s = atomicAdd(&cnt[p], 1); idx[p][s] = base + 3; }
                }
            }
        }
    }
    __syncthreads();

    const int wc = cnt[0];
    const int bc = cnt[1];

    // ---- Phase B: float4 gather from L2-hot g_ftw_t ----
    const int c  = tid & 63;
    const int fg = tid >> 6;
    const float4* __restrict__ ftw4 = reinterpret_cast<const float4*>(g_ftw_t);

    float4 aw = make_float4(0.f, 0.f, 0.f, 0.f);
    float4 ab = make_float4(0.f, 0.f, 0.f, 0.f);
#pragma unroll 4
    for (int j = fg; j < wc; j += 4) {
        float4 v = ftw4[(size_t)idx[0][j] * 64 + c];
        aw.x += v.x; aw.y += v.y; aw.z += v.z; aw.w += v.w;
    }
#pragma unroll 4
    for (int j = fg; j < bc; j += 4) {
        float4 v = ftw4[(size_t)idx[1][j] * 64 + c];
        ab.x += v.x; ab.y += v.y; ab.z += v.z; ab.w += v.w;
    }
    red[0][fg][c] = aw;
    red[1][fg][c] = ab;
    __syncthreads();

    const bool s = (stm[b] != 0.f);

    if (tid < 128) {
        int p  = tid >> 6;
        int cc = tid & 63;
        float4 v0 = red[p][0][cc], v1 = red[p][1][cc];
        float4 v2 = red[p][2][cc], v3 = red[p][3][cc];
        float4 bi = reinterpret_cast<const float4*>(ft_b)[cc];
        float4 r;
        r.x = fminf(fmaxf(v0.x + v1.x + v2.x + v3.x + bi.x, 0.f), 1.f);
        r.y = fminf(fmaxf(v0.y + v1.y + v2.y + v3.y + bi.y, 0.f), 1.f);
        r.z = fminf(fmaxf(v0.z + v1.z + v2.z + v3.z + bi.z, 0.f), 1.f);
        r.w = fminf(fmaxf(v0.w + v1.w + v2.w + v3.w + bi.w, 0.f), 1.f);
        int half = ((p == 0) == s) ? 0 : 1;
        reinterpret_cast<float4*>(hid)[half * 64 + cc] = r;
    }
    __syncthreads();

    // ---- Phase C: MLP ----
    // Layer 1: 512 -> 32, 8 threads per output
    {
        int k  = tid >> 3;
        int s8 = tid & 7;
        const float* w = l1w + k * 512;
        float p = 0.f;
#pragma unroll
        for (int j = s8; j < 512; j += 8) p += hid[j] * w[j];
        p += __shfl_down_sync(0xffffffffu, p, 4, 8);
        p += __shfl_down_sync(0xffffffffu, p, 2, 8);
        p += __shfl_down_sync(0xffffffffu, p, 1, 8);
        if (s8 == 0) x1s[k] = fminf(fmaxf(p + l1b[k], 0.f), 1.f);
    }
    __syncthreads();

    // Layer 2: 32 -> 32
    if (tid < 32) {
        float p = l2b[tid];
        const float* w = l2w + tid * 32;
#pragma unroll
        for (int j = 0; j < 32; ++j) p += x1s[j] * w[j];
        x2s[tid] = fminf(fmaxf(p, 0.f), 1.f);
    }
    __syncwarp(0xffffffffu);

    // Layer 3: 32 -> 1
    if (tid < 32) {
        float p = x2s[tid] * l3w[tid];
        p += __shfl_down_sync(0xffffffffu, p, 16);
        p += __shfl_down_sync(0xffffffffu, p, 8);
        p += __shfl_down_sync(0xffffffffu, p, 4);
        p += __shfl_down_sync(0xffffffffu, p, 2);
        p += __shfl_down_sync(0xffffffffu, p, 1);
        if (tid == 0) out[b] = p + l3b[0];
    }
}

// ---------------------------------------------------------------------------
// Launch
// ---------------------------------------------------------------------------
extern "C" void kernel_launch(void* const* d_in, const int* in_sizes, int n_in,
                              void* d_out, int out_size) {
    const float* white = (const float*)d_in[0];
    const float* black = (const float*)d_in[1];
    const float* stm   = (const float*)d_in[2];
    const float* ft_w  = (const float*)d_in[3];
    const float* ft_b  = (const float*)d_in[4];
    const float* l1w   = (const float*)d_in[5];
    const float* l1b   = (const float*)d_in[6];
    const float* l2w   = (const float*)d_in[7];
    const float* l2b   = (const float*)d_in[8];
    const float* l3w   = (const float*)d_in[9];
    const float* l3b   = (const float*)d_in[10];
    float* out = (float*)d_out;

    dim3 tb(32, 8);
    dim3 tg(IN_SZ / 32, HID / 32);
    transpose_ft<<<tg, tb>>>(ft_w);

    nnue_fused<<<BATCH, 256>>>(white, black, stm, ft_b,
                               l1w, l1b, l2w, l2b, l3w, l3b, out);
}